// round 13
// baseline (speedup 1.0000x reference)
#include <cuda_runtime.h>

// ---------------------------------------------------------------------------
// QHashSoftmax: LUT fixed-point softmax, exact-integer reformulation.
//   idx = clamp(rne(x*16), -128, 127) & 255            (cvt.rni.sat.s8)
//   k[idx] = clip(rint(exp(signed(idx)/16 * scale)*128), 0, 127)   (u8 LUT)
//   S = sum(k) over 1024-element row   (exact integer, <= 130048)
//   t = min(floor(S/k), 1023)   (k=0 -> 1023)  [fp32 div+floor exact here]
//   out = tdiv8[t]/128, tdiv8[t] = min(rne(f32(1/t)*128), 127)  (t=0 -> 127)
//
// Structure (R13: cp.async double-buffered pipeline, cooperative family):
//  - 256-thread block processes 8 groups x 4 rows (32 rows, grid 1536).
//  - group g+2 prefetched via cp.async.cg (L1 bypass) into xbuf[g&1] while
//    group g computes: DRAM read stream decoupled from the compute chain.
//  - per group: quantize (cvt.rni.sat.s8) -> sk8 gather -> dp4a -> packed-pair
//    REDUX -> 2x64-bit atomics -> per-group ocode[4][128] (one exact fp32 div
//    + tdiv8 byte LUT per entry) -> conflict-free gather -> .cs stores.
//  - ocode/sS64 double-buffered: 3 barriers per 4-row group.
//  - setup spread over 8 blocks (serial fp64-exp cost ~1.5us).
// ---------------------------------------------------------------------------

__device__ unsigned char g_exp_u8[256];    // wrapped-code -> k
__device__ unsigned char g_div_u8[1024];   // t -> output code (scale-indep)

__global__ void qhs_setup_kernel(const float* __restrict__ scale_ptr) {
    const int b = blockIdx.x, t = threadIdx.x;   // 8 blocks x 128 threads
    if (t < 32) {
        int i = b * 32 + t;                      // exp entry
        float scale = *scale_ptr;
        int sv = (i >= 128) ? (i - 256) : i;     // two's-complement decode
        float val = (float)sv * 0.0625f * scale; // fp32, matches reference
        double e = exp((double)val);             // high-precision exp
        double r = rint(e * 128.0);              // round half to even
        if (r > 127.0) r = 127.0;
        if (r < 0.0)   r = 0.0;
        g_exp_u8[i] = (unsigned char)(int)r;
    }
    // reciprocal table: fp32 correctly-rounded 1/t (faithful to jnp f32 div),
    // *128 exact, round-half-even, clip 127; t=0 -> +inf -> 127.
    int tdx = b * 128 + t;
    float inv = __fdiv_rn(1.0f, (float)tdx);
    float code = fminf(rintf(inv * 128.0f), 127.0f);
    g_div_u8[tdx] = (unsigned char)(int)code;
}

// clamp(round-half-even(f), -128, 127) & 255 in one convert + one mask
__device__ __forceinline__ unsigned qhs_code(float f) {
    int r;
    asm("cvt.rni.sat.s8.f32 %0, %1;" : "=r"(r) : "f"(f));
    return (unsigned)r & 255u;
}

// 16-byte cp.async, L1-bypassing (.cg)
__device__ __forceinline__ void cpa16(void* smem_dst, const void* gsrc) {
    unsigned sa = (unsigned)__cvta_generic_to_shared(smem_dst);
    asm volatile("cp.async.cg.shared.global [%0], [%1], 16;"
                 :: "r"(sa), "l"(gsrc));
}

#define GROUPS 8
#define GRP_F4 1024     // 4 rows x 256 float4 = 16KB

__global__ __launch_bounds__(256, 6) void qhs_main_kernel(
    const float4* __restrict__ x, float4* __restrict__ out)
{
    __shared__ float4 xbuf[2][GRP_F4];                 // 32KB double buffer
    __shared__ unsigned char sk8[256];                 // exp codes
    __shared__ unsigned char tdiv8[1024];              // t -> out code
    __shared__ unsigned char ocode[2][4][128];         // per-group out tables
    __shared__ unsigned long long sS64[2][2];          // packed row sums

    const int tid = threadIdx.x;
    const long long gbase = (long long)blockIdx.x * (GROUPS * GRP_F4);

    // prologue: prefetch groups 0,1 first so DRAM starts immediately
#pragma unroll
    for (int g = 0; g < 2; g++) {
#pragma unroll
        for (int r = 0; r < 4; r++)
            cpa16(&xbuf[g][r * 256 + tid],
                  &x[gbase + g * GRP_F4 + r * 256 + tid]);
        asm volatile("cp.async.commit_group;");
    }

    // stage tables + zero sums (overlaps with in-flight prefetch)
    sk8[tid] = g_exp_u8[tid];
    ((unsigned*)tdiv8)[tid] = ((const unsigned*)g_div_u8)[tid];
    if (tid < 4) ((unsigned long long*)sS64)[tid] = 0ull;

    for (int g = 0; g < GROUPS; g++) {
        const int b = g & 1;
        if (g < GROUPS - 1) asm volatile("cp.async.wait_group 1;");
        else                asm volatile("cp.async.wait_group 0;");
        __syncthreads();     // group g data visible to all threads

        // ---- phase 1: quantize -> gather k -> dp4a -> packed redux ------
        unsigned pk[4], d[4];
#pragma unroll
        for (int r = 0; r < 4; r++) {
            float4 v = xbuf[b][r * 256 + tid];
            unsigned p = qhs_code(v.x * 16.0f)
                       | (qhs_code(v.y * 16.0f) << 8)
                       | (qhs_code(v.z * 16.0f) << 16)
                       | (qhs_code(v.w * 16.0f) << 24);
            unsigned k0 = sk8[p & 255u];
            unsigned k1 = sk8[(p >> 8) & 255u];
            unsigned k2 = sk8[(p >> 16) & 255u];
            unsigned k3 = sk8[p >> 24];
            pk[r] = k0 | (k1 << 8) | (k2 << 16) | (k3 << 24);
            d[r] = __dp4a(pk[r], 0x01010101u, 0u);     // <= 508
        }
        // rows (0,1)/(2,3) in 16-bit halves; 32-lane sums <= 16256, no carry
        unsigned s01 = __reduce_add_sync(0xFFFFFFFFu, d[0] | (d[1] << 16));
        unsigned s23 = __reduce_add_sync(0xFFFFFFFFu, d[2] | (d[3] << 16));
        if ((tid & 31) == 0) {
            atomicAdd(&sS64[b][0],
                      (unsigned long long)(s01 & 0xFFFFu) |
                      ((unsigned long long)(s01 >> 16) << 32));
            atomicAdd(&sS64[b][1],
                      (unsigned long long)(s23 & 0xFFFFu) |
                      ((unsigned long long)(s23 >> 16) << 32));
        }
        __syncthreads();     // B1: sums done; xbuf[b] fully consumed

        // refill xbuf[b] with group g+2 while phases 2/3 run
        if (g + 2 < GROUPS) {
#pragma unroll
            for (int r = 0; r < 4; r++)
                cpa16(&xbuf[b][r * 256 + tid],
                      &x[gbase + (g + 2) * GRP_F4 + r * 256 + tid]);
            asm volatile("cp.async.commit_group;");
        }

        // ---- phase 2: per-group out tables (2 entries per thread) -------
        const unsigned* sS32 = (const unsigned*)&sS64[b][0];  // rows 0..3
#pragma unroll
        for (int e = tid; e < 512; e += 256) {
            int rw = e >> 7, kk = e & 127;
            // floor(S/k): IEEE div+floor exact; kk=0 -> +inf -> 1023;
            // tdiv8 handles t=0 -> 127 (reference saturations).
            float t = fminf(floorf(__fdiv_rn((float)sS32[rw], (float)kk)),
                            1023.0f);
            ocode[b][rw][kk] = tdiv8[(int)t];
        }
        __syncthreads();     // B2: tables ready
        if (tid < 2) sS64[b][tid] = 0ull;    // reset for group g+2

        // ---- phase 3: conflict-free gathers + coalesced .cs stores ------
#pragma unroll
        for (int r = 0; r < 4; r++) {
            unsigned p = pk[r];
            float4 o;
            o.x = (float)ocode[b][r][p & 255u]         * 0.0078125f;
            o.y = (float)ocode[b][r][(p >> 8) & 255u]  * 0.0078125f;
            o.z = (float)ocode[b][r][(p >> 16) & 255u] * 0.0078125f;
            o.w = (float)ocode[b][r][p >> 24]          * 0.0078125f;
            __stcs(&out[gbase + g * GRP_F4 + r * 256 + tid], o);
        }
    }
}

extern "C" void kernel_launch(void* const* d_in, const int* in_sizes, int n_in,
                              void* d_out, int out_size) {
    const float* x     = (const float*)d_in[0];   // [4,12,1024,1024] fp32
    const float* scale = (const float*)d_in[1];   // scalar fp32

    const int n_elems = in_sizes[0];
    const int n_rows  = n_elems >> 10;                   // rows of 1024
    const int n_blocks = n_rows / (GROUPS * 4);          // 32 rows/block

    qhs_setup_kernel<<<8, 128>>>(scale);
    qhs_main_kernel<<<n_blocks, 256>>>((const float4*)x, (float4*)d_out);
}

// round 14
// speedup vs baseline: 1.1499x; 1.1499x over previous
#include <cuda_runtime.h>

// ---------------------------------------------------------------------------
// QHashSoftmax: LUT fixed-point softmax, exact-integer reformulation.
//   idx = clamp(rne(x*16), -128, 127) & 255            (cvt.rni.sat.s8)
//   k[idx] = clip(rint(exp(signed(idx)/16 * scale)*128), 0, 127)   (u8 LUT)
//   S = sum(k) over 1024-element row   (exact integer, <= 130048)
//   t = min(floor(S/k), 1023)   (k=0 -> 1023)  [fp32 div+floor exact here]
//   out = tdiv8[t]/128, tdiv8[t] = min(rne(128/t), 127)   (t=0 -> 127)
//     [rne(128/t) == 128*rne(1/t): pow2 scaling commutes with rounding]
//
// Structure (R14 = best-bench R6 kernel + in-block reciprocal LUT):
//  - 4 rows / 256-thread block, thread t = float4 index t of each row
//    (rows at +256): every LDG/STG per-instruction fully coalesced.
//  - tdiv8[1024] built per block (4 fp32 divs/thread), overlapped with the
//    initial loads -> phase 2 needs ONE div + byte LUT per entry; setup
//    kernel unchanged (exp table only, the low-bench-gap variant).
//  - byte-packed codes, dp4a partials, packed-pair REDUX (16-bit halves,
//    32-lane sums <= 16256, no carry), 4x32-bit smem atomics.
//  - exp table u8[256] (gather conflict deg <= 2); ocode u8[128] = 32
//    words, one/bank -> conflict-FREE gather. .cs streaming hints.
//  - __launch_bounds__(256, 6), grid 12288: the measured-best bench config.
// ---------------------------------------------------------------------------

__device__ unsigned char g_exp_u8[256];   // wrapped-code -> k

__global__ void qhs_setup_kernel(const float* __restrict__ scale_ptr) {
    int i = threadIdx.x;                      // 0..255 = wrapped address
    float scale = *scale_ptr;
    int sv = (i >= 128) ? (i - 256) : i;      // two's-complement decode
    float val = (float)sv * 0.0625f * scale;  // fp32, matches reference
    double e = exp((double)val);              // high-precision exp
    double r = rint(e * 128.0);               // round half to even
    if (r > 127.0) r = 127.0;
    if (r < 0.0)   r = 0.0;
    g_exp_u8[i] = (unsigned char)(int)r;
}

// clamp(round-half-even(f), -128, 127) & 255 in one convert + one mask
__device__ __forceinline__ unsigned qhs_code(float f) {
    int r;
    asm("cvt.rni.sat.s8.f32 %0, %1;" : "=r"(r) : "f"(f));
    return (unsigned)r & 255u;
}

#define ROWS_PER_BLOCK 4

__global__ __launch_bounds__(256, 6) void qhs_main_kernel(
    const float4* __restrict__ x, float4* __restrict__ out)
{
    __shared__ unsigned char sk8[256];                    // exp codes (u8)
    __shared__ unsigned char tdiv8[1024];                 // t -> out code
    __shared__ unsigned char ocode[ROWS_PER_BLOCK][128];  // out codes by k
    __shared__ int sS[ROWS_PER_BLOCK];                    // row sums

    const int tid = threadIdx.x;

    sk8[tid] = g_exp_u8[tid];
    if (tid < ROWS_PER_BLOCK) sS[tid] = 0;

    // Coalesced: thread t -> float4 index t of each of the block's 4 rows.
    const long long base =
        (long long)blockIdx.x * (ROWS_PER_BLOCK * 256) + tid;

    float4 v0 = __ldcs(&x[base]);
    float4 v1 = __ldcs(&x[base + 256]);
    float4 v2 = __ldcs(&x[base + 512]);
    float4 v3 = __ldcs(&x[base + 768]);

    // Build reciprocal LUT while the loads are in flight (scale-indep):
    // tdiv8[t] = min(rne(128/t), 127); t=0 -> +inf -> clipped to 127.
#pragma unroll
    for (int q = 0; q < 4; q++) {
        int t = tid + q * 256;
        float code = fminf(rintf(__fdiv_rn(128.0f, (float)t)), 127.0f);
        tdiv8[t] = (unsigned char)(int)code;
    }

    // Quantize to packed 8-bit codes (independent of tables).
    unsigned pidx[4];
#define QHS_PACK(j, v)                                                  \
    pidx[j] = qhs_code(v.x * 16.0f)          |                          \
              (qhs_code(v.y * 16.0f) << 8)   |                          \
              (qhs_code(v.z * 16.0f) << 16)  |                          \
              (qhs_code(v.w * 16.0f) << 24)
    QHS_PACK(0, v0); QHS_PACK(1, v1); QHS_PACK(2, v2); QHS_PACK(3, v3);
#undef QHS_PACK

    __syncthreads();   // sk8 + tdiv8 + sS ready

    // ---- Phase 1: gather k bytes, pack, packed-pair redux ---------------
    unsigned pk[4];
    unsigned d[4];
#pragma unroll
    for (int j = 0; j < 4; j++) {
        unsigned p = pidx[j];
        unsigned k0 = sk8[p & 255u];
        unsigned k1 = sk8[(p >> 8) & 255u];
        unsigned k2 = sk8[(p >> 16) & 255u];
        unsigned k3 = sk8[p >> 24];
        pk[j] = k0 | (k1 << 8) | (k2 << 16) | (k3 << 24);
        d[j] = __dp4a(pk[j], 0x01010101u, 0u);     // <= 508
    }
    // rows (0,1) and (2,3) in 16-bit halves; 32-lane sum <= 16256 (no carry)
    unsigned s01 = __reduce_add_sync(0xFFFFFFFFu, d[0] | (d[1] << 16));
    unsigned s23 = __reduce_add_sync(0xFFFFFFFFu, d[2] | (d[3] << 16));
    if ((tid & 31) == 0) {
        atomicAdd(&sS[0], (int)(s01 & 0xFFFFu));
        atomicAdd(&sS[1], (int)(s01 >> 16));
        atomicAdd(&sS[2], (int)(s23 & 0xFFFFu));
        atomicAdd(&sS[3], (int)(s23 >> 16));
    }

    __syncthreads();   // all sums complete

    // ---- Phase 2: per-row out tables, ONE div + LUT per entry -----------
    // 4 rows x 128 entries = 512; each thread builds 2.
#pragma unroll
    for (int e = tid; e < ROWS_PER_BLOCK * 128; e += 256) {
        int rw = e >> 7;
        int kk = e & 127;
        float Sf = (float)sS[rw];                      // exact (< 2^18)
        // floor(S/k): IEEE div then floor — exact (err < 1/k fractional gap).
        // kk==0 -> +inf -> clipped to 1023 (reference e==0 branch);
        // tdiv8 handles t==0 -> 127 (reference 1/0 saturation).
        float t = fminf(floorf(__fdiv_rn(Sf, (float)kk)), 1023.0f);
        ocode[rw][kk] = tdiv8[(int)t];
    }

    __syncthreads();   // tables ready

    // ---- Phase 3: conflict-free byte gathers + coalesced stores ---------
#pragma unroll
    for (int j = 0; j < 4; j++) {
        unsigned p = pk[j];
        float4 o;
        o.x = (float)ocode[j][p & 255u]         * 0.0078125f;
        o.y = (float)ocode[j][(p >> 8) & 255u]  * 0.0078125f;
        o.z = (float)ocode[j][(p >> 16) & 255u] * 0.0078125f;
        o.w = (float)ocode[j][p >> 24]          * 0.0078125f;
        __stcs(&out[base + j * 256], o);
    }
}

extern "C" void kernel_launch(void* const* d_in, const int* in_sizes, int n_in,
                              void* d_out, int out_size) {
    const float* x     = (const float*)d_in[0];   // [4,12,1024,1024] fp32
    const float* scale = (const float*)d_in[1];   // scalar fp32

    const int n_elems = in_sizes[0];
    const int n_rows  = n_elems >> 10;                   // rows of 1024
    const int n_blocks = n_rows / ROWS_PER_BLOCK;        // 12288

    qhs_setup_kernel<<<1, 256>>>(scale);
    qhs_main_kernel<<<n_blocks, 256>>>((const float4*)x, (float4*)d_out);
}